// round 13
// baseline (speedup 1.0000x reference)
#include <cuda_runtime.h>
#include <cuda_bf16.h>
#include <math.h>
#include <stdint.h>

#define NLEV 16
#define THASH (1u << 19)
#define EBLK 256
#define NMAX (1 << 20)
#define NBINS 65536
#define SBLK 256
#define NSEG 64

struct Res4 { int v[NLEV][4]; };

__device__ float2 g_feat[NLEV][NMAX];
__device__ float4 g_xs[NMAX];
__device__ int g_perm[NMAX];
__device__ int g_hist[NBINS];
__device__ int g_cursor[NBINS];
__device__ int g_segsum[NSEG];
__device__ unsigned long long g_w0f[16 * 32];
__device__ unsigned long long g_w1f[32 * 32];
__device__ unsigned long long g_w2f[32 * 32];

// ---- helpers ----------------------------------------------------------------
__device__ __forceinline__ uint32_t pack_bf16x2(float lo, float hi) {
    uint32_t r;
    asm("cvt.rn.bf16x2.f32 %0, %1, %2;" : "=r"(r) : "f"(hi), "f"(lo));
    return r;
}
__device__ __forceinline__ void mma16816(float* d, const uint32_t* a, uint32_t b0, uint32_t b1) {
    asm volatile("mma.sync.aligned.m16n8k16.row.col.f32.bf16.bf16.f32 "
                 "{%0,%1,%2,%3}, {%4,%5,%6,%7}, {%8,%9}, {%0,%1,%2,%3};"
                 : "+f"(d[0]), "+f"(d[1]), "+f"(d[2]), "+f"(d[3])
                 : "r"(a[0]), "r"(a[1]), "r"(a[2]), "r"(a[3]), "r"(b0), "r"(b1));
}

// ---------------------------------------------------------------------------
// Sort kernels
// ---------------------------------------------------------------------------
__device__ __forceinline__ int bucket_key(float4 xv) {
    int k0 = min((int)(xv.x * 16.0f), 15);
    int k1 = min((int)(xv.y * 16.0f), 15);
    int k2 = min((int)(xv.z * 16.0f), 15);
    int k3 = min((int)(xv.w * 16.0f), 15);
    return (((k0 * 16 + k1) * 16 + k2) * 16) + k3;
}

__global__ void sort_zero() {
    int i = blockIdx.x * SBLK + threadIdx.x;
    if (i < NBINS) g_hist[i] = 0;
}
__global__ void sort_hist(const float4* __restrict__ x, int N) {
    int n = blockIdx.x * SBLK + threadIdx.x;
    if (n >= N) return;
    atomicAdd(&g_hist[bucket_key(__ldg(x + n))], 1);
}
__global__ void __launch_bounds__(1024, 1) scan_stage1() {
    __shared__ int buf[1024];
    const int tid = threadIdx.x;
    const int base = blockIdx.x * 1024;
    int v = g_hist[base + tid];
    buf[tid] = v;
    __syncthreads();
    #pragma unroll
    for (int off = 1; off < 1024; off <<= 1) {
        int t = (tid >= off) ? buf[tid - off] : 0;
        __syncthreads();
        buf[tid] += t;
        __syncthreads();
    }
    g_cursor[base + tid] = buf[tid] - v;
    if (tid == 1023) g_segsum[blockIdx.x] = buf[1023];
}
__global__ void __launch_bounds__(64, 1) scan_stage2() {
    __shared__ int buf[NSEG];
    const int tid = threadIdx.x;
    int v = g_segsum[tid];
    buf[tid] = v;
    __syncthreads();
    #pragma unroll
    for (int off = 1; off < NSEG; off <<= 1) {
        int t = (tid >= off) ? buf[tid - off] : 0;
        __syncthreads();
        buf[tid] += t;
        __syncthreads();
    }
    g_segsum[tid] = buf[tid] - v;
}
__global__ void __launch_bounds__(1024, 1) scan_stage3() {
    const int base = blockIdx.x * 1024;
    g_cursor[base + threadIdx.x] += g_segsum[blockIdx.x];
}
__global__ void sort_scatter(const float4* __restrict__ x, int N) {
    int n = blockIdx.x * SBLK + threadIdx.x;
    if (n >= N) return;
    float4 xv = __ldg(x + n);
    int pos = atomicAdd(&g_cursor[bucket_key(xv)], 1);
    g_perm[pos] = n;
    g_xs[pos] = xv;
}

// ---------------------------------------------------------------------------
// Weight prep: fp32 [64][K] -> bf16 B fragments (m16n8k16 col-major).
// ---------------------------------------------------------------------------
__global__ void __launch_bounds__(256) prep_weights(const float* __restrict__ w0,
                                                    const float* __restrict__ w1,
                                                    const float* __restrict__ w2)
{
    const int tid = threadIdx.x;
    for (int idx = tid; idx < 16 * 32; idx += 256) {
        int frag = idx >> 5, lane = idx & 31;
        int kt = frag >> 3, nt = frag & 7;
        int n = nt * 8 + (lane >> 2);
        int kb = kt * 16 + (lane & 3) * 2;
        uint32_t b0 = pack_bf16x2(w0[n * 32 + kb],     w0[n * 32 + kb + 1]);
        uint32_t b1 = pack_bf16x2(w0[n * 32 + kb + 8], w0[n * 32 + kb + 9]);
        g_w0f[idx] = (unsigned long long)b0 | ((unsigned long long)b1 << 32);
    }
    for (int idx = tid; idx < 32 * 32; idx += 256) {
        int frag = idx >> 5, lane = idx & 31;
        int kt = frag >> 3, nt = frag & 7;
        int n = nt * 8 + (lane >> 2);
        int kb = kt * 16 + (lane & 3) * 2;
        uint32_t b0 = pack_bf16x2(w1[n * 64 + kb],     w1[n * 64 + kb + 1]);
        uint32_t b1 = pack_bf16x2(w1[n * 64 + kb + 8], w1[n * 64 + kb + 9]);
        g_w1f[idx] = (unsigned long long)b0 | ((unsigned long long)b1 << 32);
        b0 = pack_bf16x2(w2[n * 64 + kb],     w2[n * 64 + kb + 1]);
        b1 = pack_bf16x2(w2[n * 64 + kb + 8], w2[n * 64 + kb + 9]);
        g_w2f[idx] = (unsigned long long)b0 | ((unsigned long long)b1 << 32);
    }
}

// ---------------------------------------------------------------------------
// Kernel A: multi-res 4D hash encode, sorted order, with dim0 corner-pair
// merging: PRIMES[0]==1, so when base0 is even the two dim0 corners sit in
// ONE aligned float4 (idx and idx^1) -> LDG.128, one wavefront instead of two.
// ---------------------------------------------------------------------------
__global__ void __launch_bounds__(EBLK, 4)
ingp_encode(const float2* __restrict__ table, int N, Res4 res)
{
    const int i = blockIdx.x * EBLK + threadIdx.x;
    if (i >= N) return;
    const float4 xv = __ldg(&g_xs[i]);

    #pragma unroll 1
    for (int l = 0; l < NLEV; l++) {
        const float r0 = (float)res.v[l][0] - 1.0f;
        const float r1 = (float)res.v[l][1] - 1.0f;
        const float r2 = (float)res.v[l][2] - 1.0f;
        const float r3 = (float)res.v[l][3] - 1.0f;
        float p0 = xv.x * r0, p1 = xv.y * r1, p2 = xv.z * r2, p3 = xv.w * r3;
        float b0 = floorf(p0), b1 = floorf(p1), b2 = floorf(p2), b3 = floorf(p3);
        float f0 = p0 - b0, f1 = p1 - b1, f2 = p2 - b2, f3 = p3 - b3;
        float g0 = 1.f - f0, g1 = 1.f - f1, g2 = 1.f - f2, g3 = 1.f - f3;

        unsigned ha0 = (unsigned)(int)b0;                 unsigned hb0 = ha0 + 1u;
        unsigned ha1 = (unsigned)(int)b1 * 2654435761u;   unsigned hb1 = ha1 + 2654435761u;
        unsigned ha2 = (unsigned)(int)b2 * 805459861u;    unsigned hb2 = ha2 + 805459861u;
        unsigned ha3 = (unsigned)(int)b3 * 3674653429u;   unsigned hb3 = ha3 + 3674653429u;

        // xy terms grouped as dim0-pairs: (A,dim1=a) (A+1,a) (A,b) (A+1,b)
        unsigned hxy[4] = { ha0 ^ ha1, hb0 ^ ha1, ha0 ^ hb1, hb0 ^ hb1 };
        unsigned hzw[4] = { ha2 ^ ha3, hb2 ^ ha3, ha2 ^ hb3, hb2 ^ hb3 };
        float    wxy[4] = { g0 * g1,  f0 * g1,  g0 * f1,  f0 * f1 };
        float    wzw[4] = { g2 * g3,  f2 * g3,  g2 * f3,  f2 * f3 };

        const bool adj = ((ha0 & 1u) == 0u);   // base0 even -> pair adjacent
        const float2* tl = table + ((size_t)l << 19);
        float acc0 = 0.f, acc1 = 0.f;
        #pragma unroll
        for (int j = 0; j < 4; j++) {
            const unsigned hz = hzw[j];
            const float wz = wzw[j];
            #pragma unroll
            for (int p = 0; p < 2; p++) {
                unsigned i0 = (hxy[2 * p] ^ hz) & (THASH - 1u);
                float wA = wxy[2 * p] * wz;
                float wB = wxy[2 * p + 1] * wz;
                float2 e0, e1;
                if (adj) {
                    // i1 = i0 ^ 1: both corners in one aligned float4
                    float4 v = __ldg((const float4*)(tl + (i0 & ~1u)));
                    if (i0 & 1u) { e0 = make_float2(v.z, v.w); e1 = make_float2(v.x, v.y); }
                    else         { e0 = make_float2(v.x, v.y); e1 = make_float2(v.z, v.w); }
                } else {
                    unsigned i1 = (hxy[2 * p + 1] ^ hz) & (THASH - 1u);
                    e0 = __ldg(tl + i0);
                    e1 = __ldg(tl + i1);
                }
                acc0 = fmaf(wA, e0.x, acc0);
                acc1 = fmaf(wA, e0.y, acc1);
                acc0 = fmaf(wB, e1.x, acc0);
                acc1 = fmaf(wB, e1.y, acc1);
            }
        }
        g_feat[l][i] = make_float2(acc0, acc1);
    }
}

// ---------------------------------------------------------------------------
// Kernel B: HMMA (mma.sync m16n8k16 bf16) MLP. 8 warps/CTA, 16 points/warp.
// ---------------------------------------------------------------------------
__global__ void __launch_bounds__(256)
ingp_mlp_mma(const float* __restrict__ w_out, const float* __restrict__ b_out,
             float* __restrict__ out, int N)
{
    __shared__ unsigned long long s_w0f[16 * 32];
    __shared__ unsigned long long s_w1f[32 * 32];
    __shared__ unsigned long long s_w2f[32 * 32];
    __shared__ float s_wo[192];
    __shared__ float s_bo[4];

    const int tid = threadIdx.x;
    const int wid = tid >> 5;
    const int lane = tid & 31;

    for (int i = tid; i < 16 * 32; i += 256) s_w0f[i] = g_w0f[i];
    for (int i = tid; i < 32 * 32; i += 256) { s_w1f[i] = g_w1f[i]; s_w2f[i] = g_w2f[i]; }
    if (tid < 192) s_wo[tid] = w_out[tid];
    if (tid < 3)   s_bo[tid] = b_out[tid];
    __syncthreads();

    const int m0 = blockIdx.x * 128 + wid * 16;
    const int r = lane >> 2;
    const int q = lane & 3;
    const int p0 = m0 + r;
    const int p1 = m0 + r + 8;
    const bool v0 = (p0 < N), v1 = (p1 < N);
    const int i0 = v0 ? p0 : 0;
    const int i1 = v1 ? p1 : 0;

    float d[8][4];
    uint32_t a[4][4];

    #pragma unroll
    for (int kt = 0; kt < 2; kt++) {
        int lv0 = kt * 8 + q;
        int lv1 = lv0 + 4;
        float2 f00 = __ldg(&g_feat[lv0][i0]);
        float2 f01 = __ldg(&g_feat[lv0][i1]);
        float2 f10 = __ldg(&g_feat[lv1][i0]);
        float2 f11 = __ldg(&g_feat[lv1][i1]);
        a[kt][0] = pack_bf16x2(f00.x, f00.y);
        a[kt][1] = pack_bf16x2(f01.x, f01.y);
        a[kt][2] = pack_bf16x2(f10.x, f10.y);
        a[kt][3] = pack_bf16x2(f11.x, f11.y);
    }
    #pragma unroll
    for (int nt = 0; nt < 8; nt++) {
        d[nt][0] = d[nt][1] = d[nt][2] = d[nt][3] = 0.f;
        #pragma unroll
        for (int kt = 0; kt < 2; kt++) {
            unsigned long long w = s_w0f[(kt * 8 + nt) * 32 + lane];
            mma16816(d[nt], a[kt], (uint32_t)w, (uint32_t)(w >> 32));
        }
    }

    #pragma unroll
    for (int layer = 0; layer < 2; layer++) {
        const unsigned long long* s_wf = (layer == 0) ? s_w1f : s_w2f;
        #pragma unroll
        for (int kt = 0; kt < 4; kt++) {
            a[kt][0] = pack_bf16x2(fmaxf(d[2*kt][0], 0.f),   fmaxf(d[2*kt][1], 0.f));
            a[kt][1] = pack_bf16x2(fmaxf(d[2*kt][2], 0.f),   fmaxf(d[2*kt][3], 0.f));
            a[kt][2] = pack_bf16x2(fmaxf(d[2*kt+1][0], 0.f), fmaxf(d[2*kt+1][1], 0.f));
            a[kt][3] = pack_bf16x2(fmaxf(d[2*kt+1][2], 0.f), fmaxf(d[2*kt+1][3], 0.f));
        }
        #pragma unroll
        for (int nt = 0; nt < 8; nt++) {
            d[nt][0] = d[nt][1] = d[nt][2] = d[nt][3] = 0.f;
            #pragma unroll
            for (int kt = 0; kt < 4; kt++) {
                unsigned long long w = s_wf[(kt * 8 + nt) * 32 + lane];
                mma16816(d[nt], a[kt], (uint32_t)w, (uint32_t)(w >> 32));
            }
        }
    }

    {
        float o00 = 0.f, o01 = 0.f, o02 = 0.f;
        float o10 = 0.f, o11 = 0.f, o12 = 0.f;
        #pragma unroll
        for (int nt = 0; nt < 8; nt++) {
            int c = nt * 8 + q * 2;
            float h00 = fmaxf(d[nt][0], 0.f), h01 = fmaxf(d[nt][1], 0.f);
            float h10 = fmaxf(d[nt][2], 0.f), h11 = fmaxf(d[nt][3], 0.f);
            float wa0 = s_wo[c],       wb0 = s_wo[c + 1];
            float wa1 = s_wo[64 + c],  wb1 = s_wo[64 + c + 1];
            float wa2 = s_wo[128 + c], wb2 = s_wo[128 + c + 1];
            o00 = fmaf(h00, wa0, fmaf(h01, wb0, o00));
            o01 = fmaf(h00, wa1, fmaf(h01, wb1, o01));
            o02 = fmaf(h00, wa2, fmaf(h01, wb2, o02));
            o10 = fmaf(h10, wa0, fmaf(h11, wb0, o10));
            o11 = fmaf(h10, wa1, fmaf(h11, wb1, o11));
            o12 = fmaf(h10, wa2, fmaf(h11, wb2, o12));
        }
        #pragma unroll
        for (int off = 1; off <= 2; off <<= 1) {
            o00 += __shfl_xor_sync(0xFFFFFFFF, o00, off);
            o01 += __shfl_xor_sync(0xFFFFFFFF, o01, off);
            o02 += __shfl_xor_sync(0xFFFFFFFF, o02, off);
            o10 += __shfl_xor_sync(0xFFFFFFFF, o10, off);
            o11 += __shfl_xor_sync(0xFFFFFFFF, o11, off);
            o12 += __shfl_xor_sync(0xFFFFFFFF, o12, off);
        }
        if (q == 0) {
            const float b0 = s_bo[0], b1 = s_bo[1], b2 = s_bo[2];
            if (v0) {
                size_t ob = (size_t)__ldg(&g_perm[p0]) * 3;
                out[ob + 0] = b0 + o00;
                out[ob + 1] = b1 + o01;
                out[ob + 2] = b2 + o02;
            }
            if (v1) {
                size_t ob = (size_t)__ldg(&g_perm[p1]) * 3;
                out[ob + 0] = b0 + o10;
                out[ob + 1] = b1 + o11;
                out[ob + 2] = b2 + o12;
            }
        }
    }
}

extern "C" void kernel_launch(void* const* d_in, const int* in_sizes, int n_in,
                              void* d_out, int out_size)
{
    const float4* x     = (const float4*)d_in[0];
    const float2* table = (const float2*)d_in[1];
    const float*  w0    = (const float*)d_in[2];
    const float*  w1    = (const float*)d_in[3];
    const float*  w2    = (const float*)d_in[4];
    const float*  w_out = (const float*)d_in[5];
    const float*  b_out = (const float*)d_in[6];
    float* out = (float*)d_out;
    const int N = in_sizes[0] / 4;

    // Replicate numpy's RES computation bit-exactly (same aarch64 glibc pow/floor).
    Res4 res;
    const double minr[4] = {16.0, 16.0, 16.0, 16.0};
    const double maxr[4] = {256.0, 256.0, 256.0, 128.0};
    for (int d = 0; d < 4; d++) {
        double g = pow(maxr[d] / minr[d], 1.0 / 15.0);
        for (int l = 0; l < NLEV; l++) {
            res.v[l][d] = (int)floor(minr[d] * pow(g, (double)l));
        }
    }

    const int pgrid = (N + SBLK - 1) / SBLK;

    prep_weights<<<1, 256>>>(w0, w1, w2);
    sort_zero<<<(NBINS + SBLK - 1) / SBLK, SBLK>>>();
    sort_hist<<<pgrid, SBLK>>>(x, N);
    scan_stage1<<<NSEG, 1024>>>();
    scan_stage2<<<1, NSEG>>>();
    scan_stage3<<<NSEG, 1024>>>();
    sort_scatter<<<pgrid, SBLK>>>(x, N);

    int egrid = (N + EBLK - 1) / EBLK;
    ingp_encode<<<egrid, EBLK>>>(table, N, res);

    int mgrid = (N + 127) / 128;
    ingp_mlp_mma<<<mgrid, 256>>>(w_out, b_out, out, N);
}

// round 14
// speedup vs baseline: 1.0398x; 1.0398x over previous
#include <cuda_runtime.h>
#include <cuda_bf16.h>
#include <math.h>
#include <stdint.h>

#define NLEV 16
#define THASH (1u << 19)
#define EBLK 256
#define NMAX (1 << 20)
#define NBINS 65536
#define SBLK 256
#define NSEG 64

struct Res4 { int v[NLEV][4]; };

__device__ float2 g_feat[NLEV][NMAX];
__device__ float4 g_xs[NMAX];
__device__ int g_perm[NMAX];
__device__ int g_hist[NBINS];
__device__ int g_cursor[NBINS];
__device__ int g_segsum[NSEG];
__device__ unsigned long long g_w0f[16 * 32];
__device__ unsigned long long g_w1f[32 * 32];
__device__ unsigned long long g_w2f[32 * 32];

// ---- helpers ----------------------------------------------------------------
__device__ __forceinline__ uint32_t pack_bf16x2(float lo, float hi) {
    uint32_t r;
    asm("cvt.rn.bf16x2.f32 %0, %1, %2;" : "=r"(r) : "f"(hi), "f"(lo));
    return r;
}
__device__ __forceinline__ void mma16816(float* d, const uint32_t* a, uint32_t b0, uint32_t b1) {
    asm volatile("mma.sync.aligned.m16n8k16.row.col.f32.bf16.bf16.f32 "
                 "{%0,%1,%2,%3}, {%4,%5,%6,%7}, {%8,%9}, {%0,%1,%2,%3};"
                 : "+f"(d[0]), "+f"(d[1]), "+f"(d[2]), "+f"(d[3])
                 : "r"(a[0]), "r"(a[1]), "r"(a[2]), "r"(a[3]), "r"(b0), "r"(b1));
}

// ---------------------------------------------------------------------------
// Sort kernels
// ---------------------------------------------------------------------------
__device__ __forceinline__ int bucket_key(float4 xv) {
    int k0 = min((int)(xv.x * 16.0f), 15);
    int k1 = min((int)(xv.y * 16.0f), 15);
    int k2 = min((int)(xv.z * 16.0f), 15);
    int k3 = min((int)(xv.w * 16.0f), 15);
    return (((k0 * 16 + k1) * 16 + k2) * 16) + k3;
}

__global__ void sort_zero() {
    int i = blockIdx.x * SBLK + threadIdx.x;
    if (i < NBINS) g_hist[i] = 0;
}
__global__ void sort_hist(const float4* __restrict__ x, int N) {
    int n = blockIdx.x * SBLK + threadIdx.x;
    if (n >= N) return;
    atomicAdd(&g_hist[bucket_key(__ldg(x + n))], 1);
}
__global__ void __launch_bounds__(1024, 1) scan_stage1() {
    __shared__ int buf[1024];
    const int tid = threadIdx.x;
    const int base = blockIdx.x * 1024;
    int v = g_hist[base + tid];
    buf[tid] = v;
    __syncthreads();
    #pragma unroll
    for (int off = 1; off < 1024; off <<= 1) {
        int t = (tid >= off) ? buf[tid - off] : 0;
        __syncthreads();
        buf[tid] += t;
        __syncthreads();
    }
    g_cursor[base + tid] = buf[tid] - v;
    if (tid == 1023) g_segsum[blockIdx.x] = buf[1023];
}
__global__ void __launch_bounds__(64, 1) scan_stage2() {
    __shared__ int buf[NSEG];
    const int tid = threadIdx.x;
    int v = g_segsum[tid];
    buf[tid] = v;
    __syncthreads();
    #pragma unroll
    for (int off = 1; off < NSEG; off <<= 1) {
        int t = (tid >= off) ? buf[tid - off] : 0;
        __syncthreads();
        buf[tid] += t;
        __syncthreads();
    }
    g_segsum[tid] = buf[tid] - v;
}
__global__ void __launch_bounds__(1024, 1) scan_stage3() {
    const int base = blockIdx.x * 1024;
    g_cursor[base + threadIdx.x] += g_segsum[blockIdx.x];
}
__global__ void sort_scatter(const float4* __restrict__ x, int N) {
    int n = blockIdx.x * SBLK + threadIdx.x;
    if (n >= N) return;
    float4 xv = __ldg(x + n);
    int pos = atomicAdd(&g_cursor[bucket_key(xv)], 1);
    g_perm[pos] = n;
    g_xs[pos] = xv;
}

// ---------------------------------------------------------------------------
// Weight prep: fp32 [64][K] -> bf16 B fragments (m16n8k16 col-major).
// ---------------------------------------------------------------------------
__global__ void __launch_bounds__(256) prep_weights(const float* __restrict__ w0,
                                                    const float* __restrict__ w1,
                                                    const float* __restrict__ w2)
{
    const int tid = threadIdx.x;
    for (int idx = tid; idx < 16 * 32; idx += 256) {
        int frag = idx >> 5, lane = idx & 31;
        int kt = frag >> 3, nt = frag & 7;
        int n = nt * 8 + (lane >> 2);
        int kb = kt * 16 + (lane & 3) * 2;
        uint32_t b0 = pack_bf16x2(w0[n * 32 + kb],     w0[n * 32 + kb + 1]);
        uint32_t b1 = pack_bf16x2(w0[n * 32 + kb + 8], w0[n * 32 + kb + 9]);
        g_w0f[idx] = (unsigned long long)b0 | ((unsigned long long)b1 << 32);
    }
    for (int idx = tid; idx < 32 * 32; idx += 256) {
        int frag = idx >> 5, lane = idx & 31;
        int kt = frag >> 3, nt = frag & 7;
        int n = nt * 8 + (lane >> 2);
        int kb = kt * 16 + (lane & 3) * 2;
        uint32_t b0 = pack_bf16x2(w1[n * 64 + kb],     w1[n * 64 + kb + 1]);
        uint32_t b1 = pack_bf16x2(w1[n * 64 + kb + 8], w1[n * 64 + kb + 9]);
        g_w1f[idx] = (unsigned long long)b0 | ((unsigned long long)b1 << 32);
        b0 = pack_bf16x2(w2[n * 64 + kb],     w2[n * 64 + kb + 1]);
        b1 = pack_bf16x2(w2[n * 64 + kb + 8], w2[n * 64 + kb + 9]);
        g_w2f[idx] = (unsigned long long)b0 | ((unsigned long long)b1 << 32);
    }
}

// ---------------------------------------------------------------------------
// Kernel A: multi-res 4D hash encode, sorted order, BRANCHLESS dim0
// corner-pair merging: always LDG.128 the aligned pair base (covers corner0
// + neighbor i0^1); corner1 fetched with a PREDICATED ld only when it is not
// the neighbor. No BSSY/BSYNC — predicated-off lanes issue no request.
// ---------------------------------------------------------------------------
__global__ void __launch_bounds__(EBLK, 4)
ingp_encode(const float2* __restrict__ table, int N, Res4 res)
{
    const int i = blockIdx.x * EBLK + threadIdx.x;
    if (i >= N) return;
    const float4 xv = __ldg(&g_xs[i]);

    #pragma unroll 1
    for (int l = 0; l < NLEV; l++) {
        const float r0 = (float)res.v[l][0] - 1.0f;
        const float r1 = (float)res.v[l][1] - 1.0f;
        const float r2 = (float)res.v[l][2] - 1.0f;
        const float r3 = (float)res.v[l][3] - 1.0f;
        float p0 = xv.x * r0, p1 = xv.y * r1, p2 = xv.z * r2, p3 = xv.w * r3;
        float b0 = floorf(p0), b1 = floorf(p1), b2 = floorf(p2), b3 = floorf(p3);
        float f0 = p0 - b0, f1 = p1 - b1, f2 = p2 - b2, f3 = p3 - b3;
        float g0 = 1.f - f0, g1 = 1.f - f1, g2 = 1.f - f2, g3 = 1.f - f3;

        unsigned ha0 = (unsigned)(int)b0;                 unsigned hb0 = ha0 + 1u;
        unsigned ha1 = (unsigned)(int)b1 * 2654435761u;   unsigned hb1 = ha1 + 2654435761u;
        unsigned ha2 = (unsigned)(int)b2 * 805459861u;    unsigned hb2 = ha2 + 805459861u;
        unsigned ha3 = (unsigned)(int)b3 * 3674653429u;   unsigned hb3 = ha3 + 3674653429u;

        unsigned hxy[4] = { ha0 ^ ha1, hb0 ^ ha1, ha0 ^ hb1, hb0 ^ hb1 };
        unsigned hzw[4] = { ha2 ^ ha3, hb2 ^ ha3, ha2 ^ hb3, hb2 ^ hb3 };
        float    wxy[4] = { g0 * g1,  f0 * g1,  g0 * f1,  f0 * f1 };
        float    wzw[4] = { g2 * g3,  f2 * g3,  g2 * f3,  f2 * f3 };

        const float2* tl = table + ((size_t)l << 19);
        float acc0 = 0.f, acc1 = 0.f;
        #pragma unroll
        for (int j = 0; j < 4; j++) {
            const unsigned hz = hzw[j];
            const float wz = wzw[j];
            #pragma unroll
            for (int p = 0; p < 2; p++) {
                unsigned i0 = (hxy[2 * p] ^ hz) & (THASH - 1u);
                unsigned i1 = (hxy[2 * p + 1] ^ hz) & (THASH - 1u);
                float wA = wxy[2 * p] * wz;
                float wB = wxy[2 * p + 1] * wz;

                // pair-base load: covers entries i0 and i0^1 (one 32B sector)
                float4 v = __ldg((const float4*)(tl + (i0 & ~1u)));
                bool odd = (i0 & 1u);
                float2 e0 = odd ? make_float2(v.z, v.w) : make_float2(v.x, v.y);
                float2 e1 = odd ? make_float2(v.x, v.y) : make_float2(v.z, v.w); // neighbor

                // predicated fetch of corner1 when it is NOT the neighbor
                unsigned need = (i1 != (i0 ^ 1u)) ? 1u : 0u;
                asm volatile("{ .reg .pred p;\n\t"
                             "setp.ne.u32 p, %2, 0;\n\t"
                             "@p ld.global.nc.v2.f32 {%0, %1}, [%3]; }"
                             : "+f"(e1.x), "+f"(e1.y)
                             : "r"(need), "l"(tl + i1)
                             : "memory");

                acc0 = fmaf(wA, e0.x, acc0);
                acc1 = fmaf(wA, e0.y, acc1);
                acc0 = fmaf(wB, e1.x, acc0);
                acc1 = fmaf(wB, e1.y, acc1);
            }
        }
        g_feat[l][i] = make_float2(acc0, acc1);
    }
}

// ---------------------------------------------------------------------------
// Kernel B: HMMA (mma.sync m16n8k16 bf16) MLP. 8 warps/CTA, 16 points/warp.
// ---------------------------------------------------------------------------
__global__ void __launch_bounds__(256)
ingp_mlp_mma(const float* __restrict__ w_out, const float* __restrict__ b_out,
             float* __restrict__ out, int N)
{
    __shared__ unsigned long long s_w0f[16 * 32];
    __shared__ unsigned long long s_w1f[32 * 32];
    __shared__ unsigned long long s_w2f[32 * 32];
    __shared__ float s_wo[192];
    __shared__ float s_bo[4];

    const int tid = threadIdx.x;
    const int wid = tid >> 5;
    const int lane = tid & 31;

    for (int i = tid; i < 16 * 32; i += 256) s_w0f[i] = g_w0f[i];
    for (int i = tid; i < 32 * 32; i += 256) { s_w1f[i] = g_w1f[i]; s_w2f[i] = g_w2f[i]; }
    if (tid < 192) s_wo[tid] = w_out[tid];
    if (tid < 3)   s_bo[tid] = b_out[tid];
    __syncthreads();

    const int m0 = blockIdx.x * 128 + wid * 16;
    const int r = lane >> 2;
    const int q = lane & 3;
    const int p0 = m0 + r;
    const int p1 = m0 + r + 8;
    const bool v0 = (p0 < N), v1 = (p1 < N);
    const int i0 = v0 ? p0 : 0;
    const int i1 = v1 ? p1 : 0;

    float d[8][4];
    uint32_t a[4][4];

    #pragma unroll
    for (int kt = 0; kt < 2; kt++) {
        int lv0 = kt * 8 + q;
        int lv1 = lv0 + 4;
        float2 f00 = __ldg(&g_feat[lv0][i0]);
        float2 f01 = __ldg(&g_feat[lv0][i1]);
        float2 f10 = __ldg(&g_feat[lv1][i0]);
        float2 f11 = __ldg(&g_feat[lv1][i1]);
        a[kt][0] = pack_bf16x2(f00.x, f00.y);
        a[kt][1] = pack_bf16x2(f01.x, f01.y);
        a[kt][2] = pack_bf16x2(f10.x, f10.y);
        a[kt][3] = pack_bf16x2(f11.x, f11.y);
    }
    #pragma unroll
    for (int nt = 0; nt < 8; nt++) {
        d[nt][0] = d[nt][1] = d[nt][2] = d[nt][3] = 0.f;
        #pragma unroll
        for (int kt = 0; kt < 2; kt++) {
            unsigned long long w = s_w0f[(kt * 8 + nt) * 32 + lane];
            mma16816(d[nt], a[kt], (uint32_t)w, (uint32_t)(w >> 32));
        }
    }

    #pragma unroll
    for (int layer = 0; layer < 2; layer++) {
        const unsigned long long* s_wf = (layer == 0) ? s_w1f : s_w2f;
        #pragma unroll
        for (int kt = 0; kt < 4; kt++) {
            a[kt][0] = pack_bf16x2(fmaxf(d[2*kt][0], 0.f),   fmaxf(d[2*kt][1], 0.f));
            a[kt][1] = pack_bf16x2(fmaxf(d[2*kt][2], 0.f),   fmaxf(d[2*kt][3], 0.f));
            a[kt][2] = pack_bf16x2(fmaxf(d[2*kt+1][0], 0.f), fmaxf(d[2*kt+1][1], 0.f));
            a[kt][3] = pack_bf16x2(fmaxf(d[2*kt+1][2], 0.f), fmaxf(d[2*kt+1][3], 0.f));
        }
        #pragma unroll
        for (int nt = 0; nt < 8; nt++) {
            d[nt][0] = d[nt][1] = d[nt][2] = d[nt][3] = 0.f;
            #pragma unroll
            for (int kt = 0; kt < 4; kt++) {
                unsigned long long w = s_wf[(kt * 8 + nt) * 32 + lane];
                mma16816(d[nt], a[kt], (uint32_t)w, (uint32_t)(w >> 32));
            }
        }
    }

    {
        float o00 = 0.f, o01 = 0.f, o02 = 0.f;
        float o10 = 0.f, o11 = 0.f, o12 = 0.f;
        #pragma unroll
        for (int nt = 0; nt < 8; nt++) {
            int c = nt * 8 + q * 2;
            float h00 = fmaxf(d[nt][0], 0.f), h01 = fmaxf(d[nt][1], 0.f);
            float h10 = fmaxf(d[nt][2], 0.f), h11 = fmaxf(d[nt][3], 0.f);
            float wa0 = s_wo[c],       wb0 = s_wo[c + 1];
            float wa1 = s_wo[64 + c],  wb1 = s_wo[64 + c + 1];
            float wa2 = s_wo[128 + c], wb2 = s_wo[128 + c + 1];
            o00 = fmaf(h00, wa0, fmaf(h01, wb0, o00));
            o01 = fmaf(h00, wa1, fmaf(h01, wb1, o01));
            o02 = fmaf(h00, wa2, fmaf(h01, wb2, o02));
            o10 = fmaf(h10, wa0, fmaf(h11, wb0, o10));
            o11 = fmaf(h10, wa1, fmaf(h11, wb1, o11));
            o12 = fmaf(h10, wa2, fmaf(h11, wb2, o12));
        }
        #pragma unroll
        for (int off = 1; off <= 2; off <<= 1) {
            o00 += __shfl_xor_sync(0xFFFFFFFF, o00, off);
            o01 += __shfl_xor_sync(0xFFFFFFFF, o01, off);
            o02 += __shfl_xor_sync(0xFFFFFFFF, o02, off);
            o10 += __shfl_xor_sync(0xFFFFFFFF, o10, off);
            o11 += __shfl_xor_sync(0xFFFFFFFF, o11, off);
            o12 += __shfl_xor_sync(0xFFFFFFFF, o12, off);
        }
        if (q == 0) {
            const float b0 = s_bo[0], b1 = s_bo[1], b2 = s_bo[2];
            if (v0) {
                size_t ob = (size_t)__ldg(&g_perm[p0]) * 3;
                out[ob + 0] = b0 + o00;
                out[ob + 1] = b1 + o01;
                out[ob + 2] = b2 + o02;
            }
            if (v1) {
                size_t ob = (size_t)__ldg(&g_perm[p1]) * 3;
                out[ob + 0] = b0 + o10;
                out[ob + 1] = b1 + o11;
                out[ob + 2] = b2 + o12;
            }
        }
    }
}

extern "C" void kernel_launch(void* const* d_in, const int* in_sizes, int n_in,
                              void* d_out, int out_size)
{
    const float4* x     = (const float4*)d_in[0];
    const float2* table = (const float2*)d_in[1];
    const float*  w0    = (const float*)d_in[2];
    const float*  w1    = (const float*)d_in[3];
    const float*  w2    = (const float*)d_in[4];
    const float*  w_out = (const float*)d_in[5];
    const float*  b_out = (const float*)d_in[6];
    float* out = (float*)d_out;
    const int N = in_sizes[0] / 4;

    // Replicate numpy's RES computation bit-exactly (same aarch64 glibc pow/floor).
    Res4 res;
    const double minr[4] = {16.0, 16.0, 16.0, 16.0};
    const double maxr[4] = {256.0, 256.0, 256.0, 128.0};
    for (int d = 0; d < 4; d++) {
        double g = pow(maxr[d] / minr[d], 1.0 / 15.0);
        for (int l = 0; l < NLEV; l++) {
            res.v[l][d] = (int)floor(minr[d] * pow(g, (double)l));
        }
    }

    const int pgrid = (N + SBLK - 1) / SBLK;

    prep_weights<<<1, 256>>>(w0, w1, w2);
    sort_zero<<<(NBINS + SBLK - 1) / SBLK, SBLK>>>();
    sort_hist<<<pgrid, SBLK>>>(x, N);
    scan_stage1<<<NSEG, 1024>>>();
    scan_stage2<<<1, NSEG>>>();
    scan_stage3<<<NSEG, 1024>>>();
    sort_scatter<<<pgrid, SBLK>>>(x, N);

    int egrid = (N + EBLK - 1) / EBLK;
    ingp_encode<<<egrid, EBLK>>>(table, N, res);

    int mgrid = (N + 127) / 128;
    ingp_mlp_mma<<<mgrid, 256>>>(w_out, b_out, out, N);
}

// round 15
// speedup vs baseline: 1.1476x; 1.1036x over previous
#include <cuda_runtime.h>
#include <cuda_bf16.h>
#include <math.h>
#include <stdint.h>

#define NLEV 16
#define THASH (1u << 19)
#define EBLK 256
#define NMAX (1 << 20)
#define NBINS 65536
#define SBLK 256
#define NSEG 64

struct Res4 { int v[NLEV][4]; };

// Feature scratch (sorted order), level-major, packed bf16x2 (one u32/level).
__device__ uint32_t g_featb[NLEV][NMAX];
__device__ float4 g_xs[NMAX];
__device__ int g_perm[NMAX];
__device__ int g_hist[NBINS];
__device__ int g_cursor[NBINS];
__device__ int g_segsum[NSEG];
__device__ unsigned long long g_w0f[16 * 32];
__device__ unsigned long long g_w1f[32 * 32];
__device__ unsigned long long g_w2f[32 * 32];

// ---- helpers ----------------------------------------------------------------
__device__ __forceinline__ uint32_t pack_bf16x2(float lo, float hi) {
    uint32_t r;
    asm("cvt.rn.bf16x2.f32 %0, %1, %2;" : "=r"(r) : "f"(hi), "f"(lo));
    return r;
}
__device__ __forceinline__ void mma16816(float* d, const uint32_t* a, uint32_t b0, uint32_t b1) {
    asm volatile("mma.sync.aligned.m16n8k16.row.col.f32.bf16.bf16.f32 "
                 "{%0,%1,%2,%3}, {%4,%5,%6,%7}, {%8,%9}, {%0,%1,%2,%3};"
                 : "+f"(d[0]), "+f"(d[1]), "+f"(d[2]), "+f"(d[3])
                 : "r"(a[0]), "r"(a[1]), "r"(a[2]), "r"(a[3]), "r"(b0), "r"(b1));
}

__device__ __forceinline__ int bucket_key(float4 xv) {
    int k0 = min((int)(xv.x * 16.0f), 15);
    int k1 = min((int)(xv.y * 16.0f), 15);
    int k2 = min((int)(xv.z * 16.0f), 15);
    int k3 = min((int)(xv.w * 16.0f), 15);
    return (((k0 * 16 + k1) * 16 + k2) * 16) + k3;
}

// ---------------------------------------------------------------------------
// Setup: blocks [0,256) zero the histogram; block 256 preps weight fragments.
// (Every fragment entry is fully written -> no zero-init needed for weights.)
// ---------------------------------------------------------------------------
__global__ void __launch_bounds__(SBLK) setup_kernel(const float* __restrict__ w0,
                                                     const float* __restrict__ w1,
                                                     const float* __restrict__ w2)
{
    const int tid = threadIdx.x;
    if (blockIdx.x < 256) {
        int i = blockIdx.x * SBLK + tid;
        if (i < NBINS) g_hist[i] = 0;
        return;
    }
    // weight fragment prep (fp32 -> bf16, m16n8k16 col-major B fragments)
    for (int idx = tid; idx < 16 * 32; idx += SBLK) {
        int frag = idx >> 5, lane = idx & 31;
        int kt = frag >> 3, nt = frag & 7;
        int n = nt * 8 + (lane >> 2);
        int kb = kt * 16 + (lane & 3) * 2;
        uint32_t b0 = pack_bf16x2(w0[n * 32 + kb],     w0[n * 32 + kb + 1]);
        uint32_t b1 = pack_bf16x2(w0[n * 32 + kb + 8], w0[n * 32 + kb + 9]);
        g_w0f[idx] = (unsigned long long)b0 | ((unsigned long long)b1 << 32);
    }
    for (int idx = tid; idx < 32 * 32; idx += SBLK) {
        int frag = idx >> 5, lane = idx & 31;
        int kt = frag >> 3, nt = frag & 7;
        int n = nt * 8 + (lane >> 2);
        int kb = kt * 16 + (lane & 3) * 2;
        uint32_t b0 = pack_bf16x2(w1[n * 64 + kb],     w1[n * 64 + kb + 1]);
        uint32_t b1 = pack_bf16x2(w1[n * 64 + kb + 8], w1[n * 64 + kb + 9]);
        g_w1f[idx] = (unsigned long long)b0 | ((unsigned long long)b1 << 32);
        b0 = pack_bf16x2(w2[n * 64 + kb],     w2[n * 64 + kb + 1]);
        b1 = pack_bf16x2(w2[n * 64 + kb + 8], w2[n * 64 + kb + 9]);
        g_w2f[idx] = (unsigned long long)b0 | ((unsigned long long)b1 << 32);
    }
}

__global__ void sort_hist(const float4* __restrict__ x, int N) {
    int n = blockIdx.x * SBLK + threadIdx.x;
    if (n >= N) return;
    atomicAdd(&g_hist[bucket_key(__ldg(x + n))], 1);
}
__global__ void __launch_bounds__(1024, 1) scan_stage1() {
    __shared__ int buf[1024];
    const int tid = threadIdx.x;
    const int base = blockIdx.x * 1024;
    int v = g_hist[base + tid];
    buf[tid] = v;
    __syncthreads();
    #pragma unroll
    for (int off = 1; off < 1024; off <<= 1) {
        int t = (tid >= off) ? buf[tid - off] : 0;
        __syncthreads();
        buf[tid] += t;
        __syncthreads();
    }
    g_cursor[base + tid] = buf[tid] - v;
    if (tid == 1023) g_segsum[blockIdx.x] = buf[1023];
}
__global__ void __launch_bounds__(64, 1) scan_stage2() {
    __shared__ int buf[NSEG];
    const int tid = threadIdx.x;
    int v = g_segsum[tid];
    buf[tid] = v;
    __syncthreads();
    #pragma unroll
    for (int off = 1; off < NSEG; off <<= 1) {
        int t = (tid >= off) ? buf[tid - off] : 0;
        __syncthreads();
        buf[tid] += t;
        __syncthreads();
    }
    g_segsum[tid] = buf[tid] - v;
}
__global__ void __launch_bounds__(1024, 1) scan_stage3() {
    const int base = blockIdx.x * 1024;
    g_cursor[base + threadIdx.x] += g_segsum[blockIdx.x];
}
__global__ void sort_scatter(const float4* __restrict__ x, int N) {
    int n = blockIdx.x * SBLK + threadIdx.x;
    if (n >= N) return;
    float4 xv = __ldg(x + n);
    int pos = atomicAdd(&g_cursor[bucket_key(xv)], 1);
    g_perm[pos] = n;
    g_xs[pos] = xv;
}

// ---------------------------------------------------------------------------
// Kernel A: multi-res 4D hash encode (R12-proven loop), sorted order,
// output packed bf16x2 (identical values to the MLP-side pack it replaces).
// ---------------------------------------------------------------------------
__global__ void __launch_bounds__(EBLK, 4)
ingp_encode(const float2* __restrict__ table, int N, Res4 res)
{
    const int i = blockIdx.x * EBLK + threadIdx.x;
    if (i >= N) return;
    const float4 xv = __ldg(&g_xs[i]);

    #pragma unroll 1
    for (int l = 0; l < NLEV; l++) {
        const float r0 = (float)res.v[l][0] - 1.0f;
        const float r1 = (float)res.v[l][1] - 1.0f;
        const float r2 = (float)res.v[l][2] - 1.0f;
        const float r3 = (float)res.v[l][3] - 1.0f;
        float p0 = xv.x * r0, p1 = xv.y * r1, p2 = xv.z * r2, p3 = xv.w * r3;
        float b0 = floorf(p0), b1 = floorf(p1), b2 = floorf(p2), b3 = floorf(p3);
        float f0 = p0 - b0, f1 = p1 - b1, f2 = p2 - b2, f3 = p3 - b3;
        float g0 = 1.f - f0, g1 = 1.f - f1, g2 = 1.f - f2, g3 = 1.f - f3;

        unsigned ha0 = (unsigned)(int)b0;                 unsigned hb0 = ha0 + 1u;
        unsigned ha1 = (unsigned)(int)b1 * 2654435761u;   unsigned hb1 = ha1 + 2654435761u;
        unsigned ha2 = (unsigned)(int)b2 * 805459861u;    unsigned hb2 = ha2 + 805459861u;
        unsigned ha3 = (unsigned)(int)b3 * 3674653429u;   unsigned hb3 = ha3 + 3674653429u;

        unsigned hxy[4] = { ha0 ^ ha1, hb0 ^ ha1, ha0 ^ hb1, hb0 ^ hb1 };
        unsigned hzw[4] = { ha2 ^ ha3, hb2 ^ ha3, ha2 ^ hb3, hb2 ^ hb3 };
        float    wxy[4] = { g0 * g1,  f0 * g1,  g0 * f1,  f0 * f1 };
        float    wzw[4] = { g2 * g3,  f2 * g3,  g2 * f3,  f2 * f3 };

        const float2* tl = table + ((size_t)l << 19);
        float acc0 = 0.f, acc1 = 0.f;
        #pragma unroll
        for (int c = 0; c < 16; c++) {
            unsigned idx = (hxy[c & 3] ^ hzw[(c >> 2) & 3]) & (THASH - 1u);
            float2 t2 = __ldg(tl + idx);
            float w = wxy[c & 3] * wzw[(c >> 2) & 3];
            acc0 = fmaf(w, t2.x, acc0);
            acc1 = fmaf(w, t2.y, acc1);
        }
        g_featb[l][i] = pack_bf16x2(acc0, acc1);
    }
}

// ---------------------------------------------------------------------------
// Kernel B: HMMA (mma.sync m16n8k16 bf16) MLP. 8 warps/CTA, 16 points/warp.
// Feature loads are now single u32 bf16x2 (pre-packed by encode).
// ---------------------------------------------------------------------------
__global__ void __launch_bounds__(256)
ingp_mlp_mma(const float* __restrict__ w_out, const float* __restrict__ b_out,
             float* __restrict__ out, int N)
{
    __shared__ unsigned long long s_w0f[16 * 32];
    __shared__ unsigned long long s_w1f[32 * 32];
    __shared__ unsigned long long s_w2f[32 * 32];
    __shared__ float s_wo[192];
    __shared__ float s_bo[4];

    const int tid = threadIdx.x;
    const int wid = tid >> 5;
    const int lane = tid & 31;

    for (int i = tid; i < 16 * 32; i += 256) s_w0f[i] = g_w0f[i];
    for (int i = tid; i < 32 * 32; i += 256) { s_w1f[i] = g_w1f[i]; s_w2f[i] = g_w2f[i]; }
    if (tid < 192) s_wo[tid] = w_out[tid];
    if (tid < 3)   s_bo[tid] = b_out[tid];
    __syncthreads();

    const int m0 = blockIdx.x * 128 + wid * 16;
    const int r = lane >> 2;
    const int q = lane & 3;
    const int p0 = m0 + r;
    const int p1 = m0 + r + 8;
    const bool v0 = (p0 < N), v1 = (p1 < N);
    const int i0 = v0 ? p0 : 0;
    const int i1 = v1 ? p1 : 0;

    float d[8][4];
    uint32_t a[4][4];

    // ---- layer 0: A fragments straight from packed features ----
    #pragma unroll
    for (int kt = 0; kt < 2; kt++) {
        int lv0 = kt * 8 + q;
        int lv1 = lv0 + 4;
        a[kt][0] = __ldg(&g_featb[lv0][i0]);
        a[kt][1] = __ldg(&g_featb[lv0][i1]);
        a[kt][2] = __ldg(&g_featb[lv1][i0]);
        a[kt][3] = __ldg(&g_featb[lv1][i1]);
    }
    #pragma unroll
    for (int nt = 0; nt < 8; nt++) {
        d[nt][0] = d[nt][1] = d[nt][2] = d[nt][3] = 0.f;
        #pragma unroll
        for (int kt = 0; kt < 2; kt++) {
            unsigned long long w = s_w0f[(kt * 8 + nt) * 32 + lane];
            mma16816(d[nt], a[kt], (uint32_t)w, (uint32_t)(w >> 32));
        }
    }

    // ---- layers 1 & 2 ----
    #pragma unroll
    for (int layer = 0; layer < 2; layer++) {
        const unsigned long long* s_wf = (layer == 0) ? s_w1f : s_w2f;
        #pragma unroll
        for (int kt = 0; kt < 4; kt++) {
            a[kt][0] = pack_bf16x2(fmaxf(d[2*kt][0], 0.f),   fmaxf(d[2*kt][1], 0.f));
            a[kt][1] = pack_bf16x2(fmaxf(d[2*kt][2], 0.f),   fmaxf(d[2*kt][3], 0.f));
            a[kt][2] = pack_bf16x2(fmaxf(d[2*kt+1][0], 0.f), fmaxf(d[2*kt+1][1], 0.f));
            a[kt][3] = pack_bf16x2(fmaxf(d[2*kt+1][2], 0.f), fmaxf(d[2*kt+1][3], 0.f));
        }
        #pragma unroll
        for (int nt = 0; nt < 8; nt++) {
            d[nt][0] = d[nt][1] = d[nt][2] = d[nt][3] = 0.f;
            #pragma unroll
            for (int kt = 0; kt < 4; kt++) {
                unsigned long long w = s_wf[(kt * 8 + nt) * 32 + lane];
                mma16816(d[nt], a[kt], (uint32_t)w, (uint32_t)(w >> 32));
            }
        }
    }

    // ---- final layer + quad reduce ----
    {
        float o00 = 0.f, o01 = 0.f, o02 = 0.f;
        float o10 = 0.f, o11 = 0.f, o12 = 0.f;
        #pragma unroll
        for (int nt = 0; nt < 8; nt++) {
            int c = nt * 8 + q * 2;
            float h00 = fmaxf(d[nt][0], 0.f), h01 = fmaxf(d[nt][1], 0.f);
            float h10 = fmaxf(d[nt][2], 0.f), h11 = fmaxf(d[nt][3], 0.f);
            float wa0 = s_wo[c],       wb0 = s_wo[c + 1];
            float wa1 = s_wo[64 + c],  wb1 = s_wo[64 + c + 1];
            float wa2 = s_wo[128 + c], wb2 = s_wo[128 + c + 1];
            o00 = fmaf(h00, wa0, fmaf(h01, wb0, o00));
            o01 = fmaf(h00, wa1, fmaf(h01, wb1, o01));
            o02 = fmaf(h00, wa2, fmaf(h01, wb2, o02));
            o10 = fmaf(h10, wa0, fmaf(h11, wb0, o10));
            o11 = fmaf(h10, wa1, fmaf(h11, wb1, o11));
            o12 = fmaf(h10, wa2, fmaf(h11, wb2, o12));
        }
        #pragma unroll
        for (int off = 1; off <= 2; off <<= 1) {
            o00 += __shfl_xor_sync(0xFFFFFFFF, o00, off);
            o01 += __shfl_xor_sync(0xFFFFFFFF, o01, off);
            o02 += __shfl_xor_sync(0xFFFFFFFF, o02, off);
            o10 += __shfl_xor_sync(0xFFFFFFFF, o10, off);
            o11 += __shfl_xor_sync(0xFFFFFFFF, o11, off);
            o12 += __shfl_xor_sync(0xFFFFFFFF, o12, off);
        }
        if (q == 0) {
            const float b0 = s_bo[0], b1 = s_bo[1], b2 = s_bo[2];
            if (v0) {
                size_t ob = (size_t)__ldg(&g_perm[p0]) * 3;
                out[ob + 0] = b0 + o00;
                out[ob + 1] = b1 + o01;
                out[ob + 2] = b2 + o02;
            }
            if (v1) {
                size_t ob = (size_t)__ldg(&g_perm[p1]) * 3;
                out[ob + 0] = b0 + o10;
                out[ob + 1] = b1 + o11;
                out[ob + 2] = b2 + o12;
            }
        }
    }
}

extern "C" void kernel_launch(void* const* d_in, const int* in_sizes, int n_in,
                              void* d_out, int out_size)
{
    const float4* x     = (const float4*)d_in[0];
    const float2* table = (const float2*)d_in[1];
    const float*  w0    = (const float*)d_in[2];
    const float*  w1    = (const float*)d_in[3];
    const float*  w2    = (const float*)d_in[4];
    const float*  w_out = (const float*)d_in[5];
    const float*  b_out = (const float*)d_in[6];
    float* out = (float*)d_out;
    const int N = in_sizes[0] / 4;

    // Replicate numpy's RES computation bit-exactly (same aarch64 glibc pow/floor).
    Res4 res;
    const double minr[4] = {16.0, 16.0, 16.0, 16.0};
    const double maxr[4] = {256.0, 256.0, 256.0, 128.0};
    for (int d = 0; d < 4; d++) {
        double g = pow(maxr[d] / minr[d], 1.0 / 15.0);
        for (int l = 0; l < NLEV; l++) {
            res.v[l][d] = (int)floor(minr[d] * pow(g, (double)l));
        }
    }

    const int pgrid = (N + SBLK - 1) / SBLK;

    setup_kernel<<<257, SBLK>>>(w0, w1, w2);      // hist zero + weight prep
    sort_hist<<<pgrid, SBLK>>>(x, N);
    scan_stage1<<<NSEG, 1024>>>();
    scan_stage2<<<1, NSEG>>>();
    scan_stage3<<<NSEG, 1024>>>();
    sort_scatter<<<pgrid, SBLK>>>(x, N);

    int egrid = (N + EBLK - 1) / EBLK;
    ingp_encode<<<egrid, EBLK>>>(table, N, res);

    int mgrid = (N + 127) / 128;
    ingp_mlp_mma<<<mgrid, 256>>>(w_out, b_out, out, N);
}